// round 10
// baseline (speedup 1.0000x reference)
#include <cuda_runtime.h>

#define TT   4096
#define NCH  32
#define NB   64
#define NP   511
#define PS   16
#define NTHREADS 512

// 4 SMEM buffers, 4112 floats each (16-float skew => bases alternate 0/16 mod 32 banks)
#define BUF_STRIDE 4112
#define SMEM_FLOATS (4 * BUF_STRIDE)
#define SMEM_BYTES  (SMEM_FLOATS * 4)

// Transposed input scratch: xT[b][n][t], contiguous in t.
__device__ float g_xT[(size_t)NB * NCH * TT];

// db4 decomposition filters (ptwt convention)
__device__ __constant__ float c_lo[8] = {
    -0.010597401784997278f,  0.032883011666982945f,  0.030841381835986965f,
    -0.18703481171888114f,  -0.02798376941698385f,   0.6308807679295904f,
     0.7148465705525415f,    0.23037781330885523f
};
__device__ __constant__ float c_hi[8] = {
    -0.23037781330885523f,   0.7148465705525415f,   -0.6308807679295904f,
    -0.02798376941698385f,   0.18703481171888114f,   0.030841381835986965f,
    -0.032883011666982945f, -0.010597401784997278f
};

// ---------------------------------------------------------------------------
// Kernel A: transpose (B, T, N) -> (B, N, T).
// Each 256-thread block handles a 128t x 32n tile (4 sub-tiles, 1 barrier).
// ---------------------------------------------------------------------------
__global__ __launch_bounds__(256)
void transpose_kernel(const float* __restrict__ x)
{
    __shared__ float tile[4][32][33];
    const int b   = blockIdx.y;
    const int t0  = blockIdx.x << 7;       // 128-t tile
    const int lin = threadIdx.x;

    // Read: float4 along n; each thread loads one row-piece per sub-tile.
    {
        const int t  = lin >> 3;
        const int n4 = (lin & 7) << 2;
        #pragma unroll
        for (int s = 0; s < 4; s++) {
            const float4 v = *(const float4*)
                &x[((size_t)b * TT + t0 + (s << 5) + t) * NCH + n4];
            tile[s][t][n4 + 0] = v.x;
            tile[s][t][n4 + 1] = v.y;
            tile[s][t][n4 + 2] = v.z;
            tile[s][t][n4 + 3] = v.w;
        }
    }
    __syncthreads();

    // Write: float4 along t; each thread writes 4 pieces of one n-row.
    {
        const int n  = lin >> 3;
        const int t4 = (lin & 7) << 2;
        float* dstRow = &g_xT[((size_t)b * NCH + n) * TT + t0];
        #pragma unroll
        for (int s = 0; s < 4; s++) {
            float4 v;
            v.x = tile[s][t4 + 0][n];
            v.y = tile[s][t4 + 1][n];
            v.z = tile[s][t4 + 2][n];
            v.w = tile[s][t4 + 3][n];
            *(float4*)&dstRow[(s << 5) + t4] = v;
        }
    }
}

// ---------------------------------------------------------------------------
// One SWT stage, 8 outputs/thread, streaming-accumulate form:
//   coef[e] = sum_j f[j] * in[t0 + e + D*(4-j)],  e in [0,8)
// Window [t0+S, t0+S+W). Element at relative offset a contributes to output e
// iff (a-e) % D == 0 and j = 4-(a-e)/D in [0,8) — pruned at compile time.
// ---------------------------------------------------------------------------
template<int D, int S, int W>
__device__ __forceinline__ void swt_stage8(const float* __restrict__ in,
                                           float* __restrict__ smemLo,
                                           float* __restrict__ smemHi,
                                           int tid)
{
    const int t0 = tid << 3;
    float lo[8] = {0.f, 0.f, 0.f, 0.f, 0.f, 0.f, 0.f, 0.f};
    float hi[8] = {0.f, 0.f, 0.f, 0.f, 0.f, 0.f, 0.f, 0.f};
    #pragma unroll
    for (int q = 0; q < W / 4; q++) {
        const float4 v = *(const float4*)&in[(t0 + S + 4 * q + TT) & (TT - 1)];
        const float elem[4] = {v.x, v.y, v.z, v.w};
        #pragma unroll
        for (int idx = 0; idx < 4; idx++) {
            const int a = S + 4 * q + idx;
            #pragma unroll
            for (int e = 0; e < 8; e++) {
                const int diff = a - e;
                if (diff % D == 0) {
                    const int j = 4 - diff / D;
                    if (j >= 0 && j < 8) {
                        lo[e] = fmaf(c_lo[j], elem[idx], lo[e]);
                        hi[e] = fmaf(c_hi[j], elem[idx], hi[e]);
                    }
                }
            }
        }
    }
    *(float4*)&smemLo[t0]     = make_float4(lo[0], lo[1], lo[2], lo[3]);
    *(float4*)&smemLo[t0 + 4] = make_float4(lo[4], lo[5], lo[6], lo[7]);
    *(float4*)&smemHi[t0]     = make_float4(hi[0], hi[1], hi[2], hi[3]);
    *(float4*)&smemHi[t0 + 4] = make_float4(hi[4], hi[5], hi[6], hi[7]);
}

// ---------------------------------------------------------------------------
// Write one 128B-line family for all patches:
//   lineOff = 0  -> channels 0,1 (bandLo=cA3, bandHi=cD3)
//   lineOff = 32 -> channels 2,3 (bandLo=cD2, bandHi=cD1)
// 8 consecutive threads build one contiguous 128B line; fully coalesced,
// LDS conflict-free per 8-lane phase (band bases differ by 16 banks).
// ---------------------------------------------------------------------------
__device__ __forceinline__ void write_lines(const float* __restrict__ bandLo,
                                            const float* __restrict__ bandHi,
                                            float* __restrict__ dstBase,
                                            int lineOff, int tid)
{
    for (int g = tid; g < NP * 8; g += NTHREADS) {
        const int p  = g >> 3;
        const int w8 = g & 7;
        const int s4 = (w8 & 3) << 2;
        const float* src = (w8 < 4) ? bandLo : bandHi;
        const float4 v = *(const float4*)&src[(p << 3) + s4];
        *(float4*)&dstBase[(size_t)p * 2048 + lineOff + (w8 << 2)] = v;
    }
}

// ---------------------------------------------------------------------------
// Kernel B: per-(b,n) row — 3-level SWT staged in 4 SMEM buffers; the
// [cD2|cD1] lines are flushed after stage 2 so stage 3 can reuse buffers.
// 65.8 KB smem x 3 blocks = 197 KB <= 228 KB; minBlocks=3 caps regs at 40.
// ---------------------------------------------------------------------------
__global__ __launch_bounds__(NTHREADS, 3)
void swt_patch_kernel(float* __restrict__ out)
{
    extern __shared__ __align__(16) float sm[];

    const int b   = blockIdx.x >> 5;
    const int n   = blockIdx.x & 31;
    const int tid = threadIdx.x;

    float* B0 = sm;                   // x   -> a2
    float* B1 = sm + 1 * BUF_STRIDE;  // a1  -> cA3
    float* B2 = sm + 2 * BUF_STRIDE;  // cD1 -> cD3
    float* B3 = sm + 3 * BUF_STRIDE;  // cD2

    // Phase L: contiguous float4 load of the transposed row (L2-resident).
    const float4* xin = (const float4*)&g_xT[((size_t)b * NCH + n) * TT];
    #pragma unroll
    for (int k = 0; k < TT / 4 / NTHREADS; k++) {
        const int i = tid + k * NTHREADS;
        *(float4*)&B0[i << 2] = xin[i];
    }
    __syncthreads();

    // Phase 1 (d=1): a1 -> B1, cD1 -> B2.  Window [-4, 12)
    swt_stage8<1, -4, 16>(B0, B1, B2, tid);
    __syncthreads();

    // Phase 2 (d=2): a2 -> B0 (x dead), cD2 -> B3.  Window [-8, 16)
    swt_stage8<2, -8, 24>(B1, B0, B3, tid);
    __syncthreads();

    // Phase 3: flush [cD2|cD1] lines (channels 2,3)
    float* dstBase = out + (size_t)b * NP * 2048 + (size_t)n * 64;
    write_lines(B3, B2, dstBase, 32, tid);
    __syncthreads();

    // Phase 4 (d=4): cA3 -> B1 (a1 dead), cD3 -> B2 (cD1 flushed).  Window [-12, 24)
    swt_stage8<4, -12, 36>(B0, B1, B2, tid);
    __syncthreads();

    // Phase 5: flush [cA3|cD3] lines (channels 0,1)
    write_lines(B1, B2, dstBase, 0, tid);
}

extern "C" void kernel_launch(void* const* d_in, const int* in_sizes, int n_in,
                              void* d_out, int out_size)
{
    const float* x = (const float*)d_in[0];
    float* out = (float*)d_out;
    (void)in_sizes; (void)n_in; (void)out_size;

    cudaFuncSetAttribute(swt_patch_kernel,
                         cudaFuncAttributeMaxDynamicSharedMemorySize,
                         SMEM_BYTES);

    dim3 tgrid(TT / 128, NB);
    transpose_kernel<<<tgrid, 256>>>(x);
    swt_patch_kernel<<<NB * NCH, NTHREADS, SMEM_BYTES>>>(out);
}

// round 12
// speedup vs baseline: 1.1161x; 1.1161x over previous
#include <cuda_runtime.h>

#define TT   4096
#define NCH  32
#define NB   64
#define NP   511
#define PS   16
#define NTHREADS 512

// 4 SMEM buffers, 4112 floats each (16-float skew => bases alternate 0/16 mod 32 banks)
//   B0 @ 0      (x, then a2)          base%32 = 0
//   B1 @ 4112   (a1, then cA3)        base%32 = 16
//   B2 @ 8224   (cD1, then cD3)       base%32 = 0
//   B3 @ 12336  (cD2)                 base%32 = 16
#define BUF_STRIDE 4112
#define SMEM_FLOATS (4 * BUF_STRIDE)
#define SMEM_BYTES  (SMEM_FLOATS * 4)

// Transposed input scratch: xT[b][n][t], contiguous in t.
__device__ float g_xT[(size_t)NB * NCH * TT];

// db4 decomposition filters (ptwt convention)
__device__ __constant__ float c_lo[8] = {
    -0.010597401784997278f,  0.032883011666982945f,  0.030841381835986965f,
    -0.18703481171888114f,  -0.02798376941698385f,   0.6308807679295904f,
     0.7148465705525415f,    0.23037781330885523f
};
__device__ __constant__ float c_hi[8] = {
    -0.23037781330885523f,   0.7148465705525415f,   -0.6308807679295904f,
    -0.02798376941698385f,   0.18703481171888114f,   0.030841381835986965f,
    -0.032883011666982945f, -0.010597401784997278f
};

// ---------------------------------------------------------------------------
// Kernel A: transpose (B, T, N) -> (B, N, T).
// Each 256-thread block handles a 128t x 32n tile (4 sub-tiles, 1 barrier).
// ---------------------------------------------------------------------------
__global__ __launch_bounds__(256)
void transpose_kernel(const float* __restrict__ x)
{
    __shared__ float tile[4][32][33];
    const int b   = blockIdx.y;
    const int t0  = blockIdx.x << 7;       // 128-t tile
    const int lin = threadIdx.x;

    // Read: float4 along n; each thread loads one row-piece per sub-tile.
    {
        const int t  = lin >> 3;
        const int n4 = (lin & 7) << 2;
        #pragma unroll
        for (int s = 0; s < 4; s++) {
            const float4 v = *(const float4*)
                &x[((size_t)b * TT + t0 + (s << 5) + t) * NCH + n4];
            tile[s][t][n4 + 0] = v.x;
            tile[s][t][n4 + 1] = v.y;
            tile[s][t][n4 + 2] = v.z;
            tile[s][t][n4 + 3] = v.w;
        }
    }
    __syncthreads();

    // Write: float4 along t; each thread writes 4 pieces of one n-row.
    {
        const int n  = lin >> 3;
        const int t4 = (lin & 7) << 2;
        float* dstRow = &g_xT[((size_t)b * NCH + n) * TT + t0];
        #pragma unroll
        for (int s = 0; s < 4; s++) {
            float4 v;
            v.x = tile[s][t4 + 0][n];
            v.y = tile[s][t4 + 1][n];
            v.z = tile[s][t4 + 2][n];
            v.w = tile[s][t4 + 3][n];
            *(float4*)&dstRow[(s << 5) + t4] = v;
        }
    }
}

// ---------------------------------------------------------------------------
// One SWT stage, 4 outputs/thread, streaming-accumulate form (low reg
// pressure): coef[e] = sum_j f[j]*in[t0 + e + D*(4-j)], e in [0,4).
// Each window element at relative offset a contributes to output e iff
// (a - e) % D == 0 and j = 4 - (a-e)/D in [0,8). All pruned at compile time.
// ---------------------------------------------------------------------------
template<int D, int S, int W>
__device__ __forceinline__ void swt_stage(const float* __restrict__ in,
                                          float* __restrict__ smemLo,
                                          float* __restrict__ smemHi,
                                          int tid)
{
    #pragma unroll
    for (int k = 0; k < TT / 4 / NTHREADS; k++) {
        const int t0 = ((tid + k * NTHREADS) << 2);
        float lo[4] = {0.f, 0.f, 0.f, 0.f};
        float hi[4] = {0.f, 0.f, 0.f, 0.f};
        #pragma unroll
        for (int q = 0; q < W / 4; q++) {
            const float4 v = *(const float4*)&in[(t0 + S + 4 * q + TT) & (TT - 1)];
            const float elem[4] = {v.x, v.y, v.z, v.w};
            #pragma unroll
            for (int idx = 0; idx < 4; idx++) {
                const int a = S + 4 * q + idx;   // offset relative to t0
                #pragma unroll
                for (int e = 0; e < 4; e++) {
                    const int diff = a - e;
                    if (diff % D == 0) {
                        const int j = 4 - diff / D;
                        if (j >= 0 && j < 8) {
                            lo[e] = fmaf(c_lo[j], elem[idx], lo[e]);
                            hi[e] = fmaf(c_hi[j], elem[idx], hi[e]);
                        }
                    }
                }
            }
        }
        *(float4*)&smemLo[t0] = make_float4(lo[0], lo[1], lo[2], lo[3]);
        *(float4*)&smemHi[t0] = make_float4(hi[0], hi[1], hi[2], hi[3]);
    }
}

// ---------------------------------------------------------------------------
// Write one 128B-line family for all patches:
//   lineOff = 0  -> channels 0,1 (bandLo=cA3, bandHi=cD3)
//   lineOff = 32 -> channels 2,3 (bandLo=cD2, bandHi=cD1)
// 8 consecutive threads build one contiguous 128B line; fully coalesced.
// ---------------------------------------------------------------------------
__device__ __forceinline__ void write_lines(const float* __restrict__ bandLo,
                                            const float* __restrict__ bandHi,
                                            float* __restrict__ dstBase,
                                            int lineOff, int tid)
{
    for (int g = tid; g < NP * 8; g += NTHREADS) {
        const int p  = g >> 3;
        const int w8 = g & 7;
        const int s4 = (w8 & 3) << 2;
        const float* src = (w8 < 4) ? bandLo : bandHi;
        const float4 v = *(const float4*)&src[(p << 3) + s4];
        *(float4*)&dstBase[(size_t)p * 2048 + lineOff + (w8 << 2)] = v;
    }
}

// ---------------------------------------------------------------------------
// Kernel B: per-(b,n) row — 3-level SWT staged in 4 SMEM buffers; the
// [cD2|cD1] lines are flushed after stage 2 so stage 3 can reuse buffers.
// 65.8 KB smem x 3 blocks = 197 KB <= 228 KB; minBlocks=3 caps regs at 40.
// ---------------------------------------------------------------------------
__global__ __launch_bounds__(NTHREADS, 3)
void swt_patch_kernel(float* __restrict__ out)
{
    extern __shared__ __align__(16) float sm[];

    const int b   = blockIdx.x >> 5;
    const int n   = blockIdx.x & 31;
    const int tid = threadIdx.x;

    float* B0 = sm;                   // x   -> a2
    float* B1 = sm + 1 * BUF_STRIDE;  // a1  -> cA3
    float* B2 = sm + 2 * BUF_STRIDE;  // cD1 -> cD3
    float* B3 = sm + 3 * BUF_STRIDE;  // cD2

    // Phase L: contiguous float4 load of the transposed row (L2-resident).
    const float4* xin = (const float4*)&g_xT[((size_t)b * NCH + n) * TT];
    #pragma unroll
    for (int k = 0; k < TT / 4 / NTHREADS; k++) {
        const int i = tid + k * NTHREADS;
        *(float4*)&B0[i << 2] = xin[i];
    }
    __syncthreads();

    // Phase 1 (d=1): a1 -> B1, cD1 -> B2
    swt_stage<1, -4, 12>(B0, B1, B2, tid);
    __syncthreads();

    // Phase 2 (d=2): a2 -> B0 (x dead), cD2 -> B3
    swt_stage<2, -8, 20>(B1, B0, B3, tid);
    __syncthreads();

    // Phase 3: flush [cD2|cD1] lines (channels 2,3)
    float* dstBase = out + (size_t)b * NP * 2048 + (size_t)n * 64;
    write_lines(B3, B2, dstBase, 32, tid);
    __syncthreads();

    // Phase 4 (d=4): cA3 -> B1 (a1 dead), cD3 -> B2 (cD1 flushed)
    swt_stage<4, -12, 32>(B0, B1, B2, tid);
    __syncthreads();

    // Phase 5: flush [cA3|cD3] lines (channels 0,1)
    write_lines(B1, B2, dstBase, 0, tid);
}

extern "C" void kernel_launch(void* const* d_in, const int* in_sizes, int n_in,
                              void* d_out, int out_size)
{
    const float* x = (const float*)d_in[0];
    float* out = (float*)d_out;
    (void)in_sizes; (void)n_in; (void)out_size;

    cudaFuncSetAttribute(swt_patch_kernel,
                         cudaFuncAttributeMaxDynamicSharedMemorySize,
                         SMEM_BYTES);

    dim3 tgrid(TT / 128, NB);
    transpose_kernel<<<tgrid, 256>>>(x);
    swt_patch_kernel<<<NB * NCH, NTHREADS, SMEM_BYTES>>>(out);
}

// round 13
// speedup vs baseline: 1.1194x; 1.0030x over previous
#include <cuda_runtime.h>
#include <cuda_fp16.h>

#define TT   4096
#define NCH  32
#define NB   64
#define NP   511
#define PS   16
#define NTHREADS 512

// SMEM layout (float granularity):
//   B0 fp32 @ 0      : x, then a2                (4096 + 16 pad)
//   B1 fp32 @ 4112   : a1; later aliased as fp16 cA3 (4096 halves)
//   H2 fp16 @ 8224   : cD1, then cD3             (4096 halves = 2048 floats + 16 pad)
//   H3 fp16 @ 10288  : cD2                       (4096 halves = 2048 floats + 16 pad)
#define OFF_B0  0
#define OFF_B1  4112
#define OFF_H2  8224
#define OFF_H3  10288
#define SMEM_FLOATS 12352
#define SMEM_BYTES  (SMEM_FLOATS * 4)   // 49408 B -> 4 blocks/SM (thread cap binds)

// Transposed input scratch: xT[b][n][t], contiguous in t.
__device__ float g_xT[(size_t)NB * NCH * TT];

// db4 decomposition filters (ptwt convention)
__device__ __constant__ float c_lo[8] = {
    -0.010597401784997278f,  0.032883011666982945f,  0.030841381835986965f,
    -0.18703481171888114f,  -0.02798376941698385f,   0.6308807679295904f,
     0.7148465705525415f,    0.23037781330885523f
};
__device__ __constant__ float c_hi[8] = {
    -0.23037781330885523f,   0.7148465705525415f,   -0.6308807679295904f,
    -0.02798376941698385f,   0.18703481171888114f,   0.030841381835986965f,
    -0.032883011666982945f, -0.010597401784997278f
};

// ---------------------------------------------------------------------------
// Kernel A: transpose (B, T, N) -> (B, N, T).
// Each 256-thread block handles a 128t x 32n tile (4 sub-tiles, 1 barrier).
// ---------------------------------------------------------------------------
__global__ __launch_bounds__(256)
void transpose_kernel(const float* __restrict__ x)
{
    __shared__ float tile[4][32][33];
    const int b   = blockIdx.y;
    const int t0  = blockIdx.x << 7;
    const int lin = threadIdx.x;

    {
        const int t  = lin >> 3;
        const int n4 = (lin & 7) << 2;
        #pragma unroll
        for (int s = 0; s < 4; s++) {
            const float4 v = *(const float4*)
                &x[((size_t)b * TT + t0 + (s << 5) + t) * NCH + n4];
            tile[s][t][n4 + 0] = v.x;
            tile[s][t][n4 + 1] = v.y;
            tile[s][t][n4 + 2] = v.z;
            tile[s][t][n4 + 3] = v.w;
        }
    }
    __syncthreads();
    {
        const int n  = lin >> 3;
        const int t4 = (lin & 7) << 2;
        float* dstRow = &g_xT[((size_t)b * NCH + n) * TT + t0];
        #pragma unroll
        for (int s = 0; s < 4; s++) {
            float4 v;
            v.x = tile[s][t4 + 0][n];
            v.y = tile[s][t4 + 1][n];
            v.z = tile[s][t4 + 2][n];
            v.w = tile[s][t4 + 3][n];
            *(float4*)&dstRow[(s << 5) + t4] = v;
        }
    }
}

// ---------------------------------------------------------------------------
// Pack 4 floats -> 4 halves (uint2, 8B aligned store).
// ---------------------------------------------------------------------------
__device__ __forceinline__ void store_half4(__half* dst, int idx,
                                            float a, float b, float c, float d)
{
    __half2 lohalf = __floats2half2_rn(a, b);
    __half2 hihalf = __floats2half2_rn(c, d);
    uint2 u;
    u.x = *(const unsigned int*)&lohalf;
    u.y = *(const unsigned int*)&hihalf;
    *(uint2*)&dst[idx] = u;
}

// ---------------------------------------------------------------------------
// One SWT stage, 4 outputs/thread, streaming-accumulate form.
// coef[e] = sum_j f[j]*in[t0 + e + D*(4-j)], e in [0,4).
// Window element at rel offset a contributes to e iff (a-e)%D==0 and
// j = 4-(a-e)/D in [0,8) — all pruned at compile time.
// LO_HALF selects fp32 vs fp16 destination for the approximation band;
// hi (detail) always goes to fp16.
// ---------------------------------------------------------------------------
template<int D, int S, int W, bool LO_HALF>
__device__ __forceinline__ void swt_stage(const float* __restrict__ in,
                                          float* __restrict__ loF,
                                          __half* __restrict__ loH,
                                          __half* __restrict__ hiH,
                                          int tid)
{
    #pragma unroll 1
    for (int k = 0; k < TT / 4 / NTHREADS; k++) {
        const int t0 = ((tid + k * NTHREADS) << 2);
        float lo[4] = {0.f, 0.f, 0.f, 0.f};
        float hi[4] = {0.f, 0.f, 0.f, 0.f};
        #pragma unroll
        for (int q = 0; q < W / 4; q++) {
            const float4 v = *(const float4*)&in[(t0 + S + 4 * q + TT) & (TT - 1)];
            const float elem[4] = {v.x, v.y, v.z, v.w};
            #pragma unroll
            for (int idx = 0; idx < 4; idx++) {
                const int a = S + 4 * q + idx;
                #pragma unroll
                for (int e = 0; e < 4; e++) {
                    const int diff = a - e;
                    if (diff % D == 0) {
                        const int j = 4 - diff / D;
                        if (j >= 0 && j < 8) {
                            lo[e] = fmaf(c_lo[j], elem[idx], lo[e]);
                            hi[e] = fmaf(c_hi[j], elem[idx], hi[e]);
                        }
                    }
                }
            }
        }
        if (LO_HALF)
            store_half4(loH, t0, lo[0], lo[1], lo[2], lo[3]);
        else
            *(float4*)&loF[t0] = make_float4(lo[0], lo[1], lo[2], lo[3]);
        store_half4(hiH, t0, hi[0], hi[1], hi[2], hi[3]);
    }
}

// ---------------------------------------------------------------------------
// Write one 128B-line family for all patches, from fp16 band buffers:
//   lineOff = 0  -> channels 0,1 (bandLo=cA3, bandHi=cD3)
//   lineOff = 32 -> channels 2,3 (bandLo=cD2, bandHi=cD1)
// 8 consecutive threads build one contiguous 128B line; fully coalesced STG.
// ---------------------------------------------------------------------------
__device__ __forceinline__ void write_lines(const __half* __restrict__ bandLo,
                                            const __half* __restrict__ bandHi,
                                            float* __restrict__ dstBase,
                                            int lineOff, int tid)
{
    for (int g = tid; g < NP * 8; g += NTHREADS) {
        const int p  = g >> 3;
        const int w8 = g & 7;
        const int s4 = (w8 & 3) << 2;
        const __half* src = (w8 < 4) ? bandLo : bandHi;
        const uint2 u = *(const uint2*)&src[(p << 3) + s4];
        const __half2 h01 = *(const __half2*)&u.x;
        const __half2 h23 = *(const __half2*)&u.y;
        const float2 f01 = __half22float2(h01);
        const float2 f23 = __half22float2(h23);
        *(float4*)&dstBase[(size_t)p * 2048 + lineOff + (w8 << 2)] =
            make_float4(f01.x, f01.y, f23.x, f23.y);
    }
}

// ---------------------------------------------------------------------------
// Kernel B: per-(b,n) row — 3-level SWT; cascade (x,a1,a2) fp32 in SMEM,
// output bands staged fp16, flushed in two fully-coalesced line passes.
// 48.3 KB smem, launch_bounds(512,4) => 64 warps/SM, regs capped at 32.
// ---------------------------------------------------------------------------
__global__ __launch_bounds__(NTHREADS, 4)
void swt_patch_kernel(float* __restrict__ out)
{
    extern __shared__ __align__(16) float sm[];

    const int b   = blockIdx.x >> 5;
    const int n   = blockIdx.x & 31;
    const int tid = threadIdx.x;

    float*  B0  = sm + OFF_B0;                    // x -> a2 (fp32)
    float*  B1  = sm + OFF_B1;                    // a1 (fp32)
    __half* B1h = (__half*)(sm + OFF_B1);         // later: cA3 (fp16 alias)
    __half* H2  = (__half*)(sm + OFF_H2);         // cD1 -> cD3 (fp16)
    __half* H3  = (__half*)(sm + OFF_H3);         // cD2 (fp16)

    // Phase L: contiguous float4 load of the transposed row (L2-resident).
    const float4* xin = (const float4*)&g_xT[((size_t)b * NCH + n) * TT];
    #pragma unroll
    for (int k = 0; k < TT / 4 / NTHREADS; k++) {
        const int i = tid + k * NTHREADS;
        *(float4*)&B0[i << 2] = xin[i];
    }
    __syncthreads();

    // Phase 1 (d=1): a1 (fp32) -> B1, cD1 (fp16) -> H2
    swt_stage<1, -4, 12, false>(B0, B1, nullptr, H2, tid);
    __syncthreads();

    // Phase 2 (d=2): a2 (fp32) -> B0 (x dead), cD2 (fp16) -> H3
    swt_stage<2, -8, 20, false>(B1, B0, nullptr, H3, tid);
    __syncthreads();

    // Phase 3: flush [cD2|cD1] lines (channels 2,3)
    float* dstBase = out + (size_t)b * NP * 2048 + (size_t)n * 64;
    write_lines(H3, H2, dstBase, 32, tid);
    __syncthreads();

    // Phase 4 (d=4): cA3 (fp16) -> B1h (a1 dead), cD3 (fp16) -> H2 (cD1 flushed)
    swt_stage<4, -12, 32, true>(B0, nullptr, B1h, H2, tid);
    __syncthreads();

    // Phase 5: flush [cA3|cD3] lines (channels 0,1)
    write_lines(B1h, H2, dstBase, 0, tid);
}

extern "C" void kernel_launch(void* const* d_in, const int* in_sizes, int n_in,
                              void* d_out, int out_size)
{
    const float* x = (const float*)d_in[0];
    float* out = (float*)d_out;
    (void)in_sizes; (void)n_in; (void)out_size;

    cudaFuncSetAttribute(swt_patch_kernel,
                         cudaFuncAttributeMaxDynamicSharedMemorySize,
                         SMEM_BYTES);

    dim3 tgrid(TT / 128, NB);
    transpose_kernel<<<tgrid, 256>>>(x);
    swt_patch_kernel<<<NB * NCH, NTHREADS, SMEM_BYTES>>>(out);
}

// round 15
// speedup vs baseline: 1.3587x; 1.2138x over previous
#include <cuda_runtime.h>
#include <cuda_fp16.h>

#define TT   4096
#define NCH  32
#define NB   64
#define NP   511
#define PS   16
#define NTHREADS 512

// SMEM layout (float granularity):
//   B0  fp32 @ 0     : x, then a2                      (4096 + 16 pad)   base%32=0
//   B1  fp32 @ 4112  : a1 (fp32)                       (4096 + 16 pad)   base%32=16
//       after stage 3 (a1 dead) B1 is re-used as two fp16 bands:
//         cA3h halves @ float 4112  (2048 floats + 16 pad)               base%32=16
//         cD3h halves @ float 6176  (2048 floats)                        base%32=0
//   H2  fp16 @ 8248  : cD1                             (2048 floats)     base%32=24
//   H3  fp16 @ 10312 : cD2                             (2048 floats)     base%32=8
// Merged-flush LDS: lanes {0-3,4-7,8-11,12-15} hit bank groups
// {16..23, 0..7, 8..15, 24..31} (+4p rot) -> all 32 banks once per phase.
#define OFF_B0   0
#define OFF_B1   4112
#define OFF_D3   6176
#define OFF_H2   8248
#define OFF_H3   10312
#define SMEM_FLOATS 12360
#define SMEM_BYTES  (SMEM_FLOATS * 4)   // 49440 B -> 4 blocks/SM

// Transposed input scratch (fp16): xTh[b][n][t], contiguous in t.
__device__ __half g_xTh[(size_t)NB * NCH * TT];

// db4 decomposition filters (ptwt convention)
__device__ __constant__ float c_lo[8] = {
    -0.010597401784997278f,  0.032883011666982945f,  0.030841381835986965f,
    -0.18703481171888114f,  -0.02798376941698385f,   0.6308807679295904f,
     0.7148465705525415f,    0.23037781330885523f
};
__device__ __constant__ float c_hi[8] = {
    -0.23037781330885523f,   0.7148465705525415f,   -0.6308807679295904f,
    -0.02798376941698385f,   0.18703481171888114f,   0.030841381835986965f,
    -0.032883011666982945f, -0.010597401784997278f
};

// ---------------------------------------------------------------------------
// Pack 4 floats -> 4 halves (uint2, 8B store).
// ---------------------------------------------------------------------------
__device__ __forceinline__ void store_half4(__half* dst, int idx,
                                            float a, float b, float c, float d)
{
    __half2 h01 = __floats2half2_rn(a, b);
    __half2 h23 = __floats2half2_rn(c, d);
    uint2 u;
    u.x = *(const unsigned int*)&h01;
    u.y = *(const unsigned int*)&h23;
    *(uint2*)&dst[idx] = u;
}

// ---------------------------------------------------------------------------
// Kernel A: transpose (B, T, N) fp32 -> (B, N, T) fp16.
// Each 256-thread block handles a 128t x 32n tile (4 sub-tiles, 1 barrier).
// ---------------------------------------------------------------------------
__global__ __launch_bounds__(256)
void transpose_kernel(const float* __restrict__ x)
{
    __shared__ float tile[4][32][33];
    const int b   = blockIdx.y;
    const int t0  = blockIdx.x << 7;
    const int lin = threadIdx.x;

    {
        const int t  = lin >> 3;
        const int n4 = (lin & 7) << 2;
        #pragma unroll
        for (int s = 0; s < 4; s++) {
            const float4 v = *(const float4*)
                &x[((size_t)b * TT + t0 + (s << 5) + t) * NCH + n4];
            tile[s][t][n4 + 0] = v.x;
            tile[s][t][n4 + 1] = v.y;
            tile[s][t][n4 + 2] = v.z;
            tile[s][t][n4 + 3] = v.w;
        }
    }
    __syncthreads();
    {
        const int n  = lin >> 3;
        const int t4 = (lin & 7) << 2;
        __half* dstRow = &g_xTh[((size_t)b * NCH + n) * TT + t0];
        #pragma unroll
        for (int s = 0; s < 4; s++) {
            store_half4(dstRow, (s << 5) + t4,
                        tile[s][t4 + 0][n], tile[s][t4 + 1][n],
                        tile[s][t4 + 2][n], tile[s][t4 + 3][n]);
        }
    }
}

// ---------------------------------------------------------------------------
// One SWT stage, 4 outputs/thread, streaming-accumulate form.
// coef[e] = sum_j f[j]*in[t0 + e + D*(4-j)], e in [0,4).
// LO_HALF selects fp32 vs fp16 destination for the approximation band;
// hi (detail) always goes to fp16.
// ---------------------------------------------------------------------------
template<int D, int S, int W, bool LO_HALF>
__device__ __forceinline__ void swt_stage(const float* __restrict__ in,
                                          float* __restrict__ loF,
                                          __half* __restrict__ loH,
                                          __half* __restrict__ hiH,
                                          int tid)
{
    #pragma unroll 1
    for (int k = 0; k < TT / 4 / NTHREADS; k++) {
        const int t0 = ((tid + k * NTHREADS) << 2);
        float lo[4] = {0.f, 0.f, 0.f, 0.f};
        float hi[4] = {0.f, 0.f, 0.f, 0.f};
        #pragma unroll
        for (int q = 0; q < W / 4; q++) {
            const float4 v = *(const float4*)&in[(t0 + S + 4 * q + TT) & (TT - 1)];
            const float elem[4] = {v.x, v.y, v.z, v.w};
            #pragma unroll
            for (int idx = 0; idx < 4; idx++) {
                const int a = S + 4 * q + idx;
                #pragma unroll
                for (int e = 0; e < 4; e++) {
                    const int diff = a - e;
                    if (diff % D == 0) {
                        const int j = 4 - diff / D;
                        if (j >= 0 && j < 8) {
                            lo[e] = fmaf(c_lo[j], elem[idx], lo[e]);
                            hi[e] = fmaf(c_hi[j], elem[idx], hi[e]);
                        }
                    }
                }
            }
        }
        if (LO_HALF)
            store_half4(loH, t0, lo[0], lo[1], lo[2], lo[3]);
        else
            *(float4*)&loF[t0] = make_float4(lo[0], lo[1], lo[2], lo[3]);
        store_half4(hiH, t0, hi[0], hi[1], hi[2], hi[3]);
    }
}

// ---------------------------------------------------------------------------
// Kernel B: per-(b,n) row — 3-level SWT; cascade fp32, bands fp16, single
// merged flush pass (both 128B-line families) with streaming stores.
// ---------------------------------------------------------------------------
__global__ __launch_bounds__(NTHREADS, 4)
void swt_patch_kernel(float* __restrict__ out)
{
    extern __shared__ __align__(16) float sm[];

    const int b   = blockIdx.x >> 5;
    const int n   = blockIdx.x & 31;
    const int tid = threadIdx.x;

    float*  B0   = sm + OFF_B0;               // x -> a2 (fp32)
    float*  B1   = sm + OFF_B1;               // a1 (fp32)
    __half* cA3h = (__half*)(sm + OFF_B1);    // stage-3 lo  (fp16, aliases a1)
    __half* cD3h = (__half*)(sm + OFF_D3);    // stage-3 hi  (fp16, aliases a1 tail)
    __half* H2   = (__half*)(sm + OFF_H2);    // cD1 (fp16)
    __half* H3   = (__half*)(sm + OFF_H3);    // cD2 (fp16)

    // Phase L: load fp16 row, expand to fp32 in B0 (two 8B loads / thread).
    const __half* xin = &g_xTh[((size_t)b * NCH + n) * TT];
    #pragma unroll
    for (int hchunk = 0; hchunk < 2; hchunk++) {
        const int hbase = hchunk * 2048 + tid * 4;
        const uint2 u = *(const uint2*)&xin[hbase];
        const float2 f01 = __half22float2(*(const __half2*)&u.x);
        const float2 f23 = __half22float2(*(const __half2*)&u.y);
        *(float4*)&B0[hbase] = make_float4(f01.x, f01.y, f23.x, f23.y);
    }
    __syncthreads();

    // Phase 1 (d=1): a1 (fp32) -> B1, cD1 (fp16) -> H2
    swt_stage<1, -4, 12, false>(B0, B1, nullptr, H2, tid);
    __syncthreads();

    // Phase 2 (d=2): a2 (fp32) -> B0 (x dead), cD2 (fp16) -> H3
    swt_stage<2, -8, 20, false>(B1, B0, nullptr, H3, tid);
    __syncthreads();

    // Phase 3 (d=4): cA3 -> cA3h, cD3 -> cD3h (both alias dead a1 in B1)
    swt_stage<4, -12, 32, true>(B0, nullptr, cA3h, cD3h, tid);
    __syncthreads();

    // Phase 4: merged flush of both line families, streaming stores.
    // g -> p = g>>4, w16 = g&15, family = w16>>3 (0: ch0,1 / 1: ch2,3),
    // w8 = w16&7; 16 consecutive lanes emit one patch's full 256B.
    float* dstBase = out + (size_t)b * NP * 2048 + (size_t)n * 64;
    for (int g = tid; g < NP * 16; g += NTHREADS) {
        const int p      = g >> 4;
        const int w16    = g & 15;
        const int family = w16 >> 3;
        const int w8     = w16 & 7;
        const int s4     = (w8 & 3) << 2;
        const __half* src = family
            ? ((w8 < 4) ? H3   : H2)      // ch2 = cD2, ch3 = cD1
            : ((w8 < 4) ? cA3h : cD3h);   // ch0 = cA3, ch1 = cD3
        const uint2 u = *(const uint2*)&src[(p << 3) + s4];
        const float2 f01 = __half22float2(*(const __half2*)&u.x);
        const float2 f23 = __half22float2(*(const __half2*)&u.y);
        __stcs((float4*)&dstBase[(size_t)p * 2048 + (w16 << 2)],
               make_float4(f01.x, f01.y, f23.x, f23.y));
    }
}

extern "C" void kernel_launch(void* const* d_in, const int* in_sizes, int n_in,
                              void* d_out, int out_size)
{
    const float* x = (const float*)d_in[0];
    float* out = (float*)d_out;
    (void)in_sizes; (void)n_in; (void)out_size;

    cudaFuncSetAttribute(swt_patch_kernel,
                         cudaFuncAttributeMaxDynamicSharedMemorySize,
                         SMEM_BYTES);

    dim3 tgrid(TT / 128, NB);
    transpose_kernel<<<tgrid, 256>>>(x);
    swt_patch_kernel<<<NB * NCH, NTHREADS, SMEM_BYTES>>>(out);
}

// round 16
// speedup vs baseline: 1.3918x; 1.0243x over previous
#include <cuda_runtime.h>
#include <cuda_fp16.h>

#define TT   4096
#define NCH  32
#define NB   64
#define NP   511
#define PS   16
#define NTHREADS 512

// All-fp16 SMEM cascade. Offsets in HALVES (buffer = 4096 halves + pad).
// Base banks (byte/4 mod 32): B0h:0, B1h:8, B2h:16, B3h:24, B4h:0.
// Merged-flush 4-lane groups read bands {B1h,B4h,B3h,B2h} = banks {8,0,24,16}
// -> 8-bank spacing tiles all 32 banks per patch.
#define OFF_B0H   0        // x   -> a2
#define OFF_B1H   4112     // a1  -> cA3
#define OFF_B2H   8224     // cD1
#define OFF_B3H   12336    // cD2
#define OFF_B4H   16448    // cD3
#define SMEM_HALVES 20560
#define SMEM_BYTES  (SMEM_HALVES * 2)   // 41120 B -> 4 blocks/SM (threads bind)

// Transposed input scratch (fp16): xTh[b][n][t], contiguous in t.
__device__ __half g_xTh[(size_t)NB * NCH * TT];

// db4 decomposition filters (ptwt convention)
__device__ __constant__ float c_lo[8] = {
    -0.010597401784997278f,  0.032883011666982945f,  0.030841381835986965f,
    -0.18703481171888114f,  -0.02798376941698385f,   0.6308807679295904f,
     0.7148465705525415f,    0.23037781330885523f
};
__device__ __constant__ float c_hi[8] = {
    -0.23037781330885523f,   0.7148465705525415f,   -0.6308807679295904f,
    -0.02798376941698385f,   0.18703481171888114f,   0.030841381835986965f,
    -0.032883011666982945f, -0.010597401784997278f
};

// ---------------------------------------------------------------------------
// Pack 4 floats -> 4 halves (uint2, 8B store).
// ---------------------------------------------------------------------------
__device__ __forceinline__ void store_half4(__half* dst, int idx,
                                            float a, float b, float c, float d)
{
    __half2 h01 = __floats2half2_rn(a, b);
    __half2 h23 = __floats2half2_rn(c, d);
    uint2 u;
    u.x = *(const unsigned int*)&h01;
    u.y = *(const unsigned int*)&h23;
    *(uint2*)&dst[idx] = u;
}

// ---------------------------------------------------------------------------
// Kernel A: transpose (B, T, N) fp32 -> (B, N, T) fp16.
// Each 256-thread block handles a 128t x 32n tile (4 sub-tiles, 1 barrier).
// ---------------------------------------------------------------------------
__global__ __launch_bounds__(256)
void transpose_kernel(const float* __restrict__ x)
{
    __shared__ float tile[4][32][33];
    const int b   = blockIdx.y;
    const int t0  = blockIdx.x << 7;
    const int lin = threadIdx.x;

    {
        const int t  = lin >> 3;
        const int n4 = (lin & 7) << 2;
        #pragma unroll
        for (int s = 0; s < 4; s++) {
            const float4 v = *(const float4*)
                &x[((size_t)b * TT + t0 + (s << 5) + t) * NCH + n4];
            tile[s][t][n4 + 0] = v.x;
            tile[s][t][n4 + 1] = v.y;
            tile[s][t][n4 + 2] = v.z;
            tile[s][t][n4 + 3] = v.w;
        }
    }
    __syncthreads();
    {
        const int n  = lin >> 3;
        const int t4 = (lin & 7) << 2;
        __half* dstRow = &g_xTh[((size_t)b * NCH + n) * TT + t0];
        #pragma unroll
        for (int s = 0; s < 4; s++) {
            store_half4(dstRow, (s << 5) + t4,
                        tile[s][t4 + 0][n], tile[s][t4 + 1][n],
                        tile[s][t4 + 2][n], tile[s][t4 + 3][n]);
        }
    }
}

// ---------------------------------------------------------------------------
// One SWT stage, 4 outputs/thread, streaming-accumulate; fp16 in / fp32
// accumulate / fp16 out.  coef[e] = sum_j f[j]*in[t0 + e + D*(4-j)].
// Window element at rel offset a contributes to e iff (a-e)%D==0 and
// j = 4-(a-e)/D in [0,8) — pruned at compile time.
// ---------------------------------------------------------------------------
template<int D, int S, int W>
__device__ __forceinline__ void swt_stage_h(const __half* __restrict__ in,
                                            __half* __restrict__ loH,
                                            __half* __restrict__ hiH,
                                            int tid)
{
    #pragma unroll 1
    for (int k = 0; k < TT / 4 / NTHREADS; k++) {
        const int t0 = ((tid + k * NTHREADS) << 2);
        float lo[4] = {0.f, 0.f, 0.f, 0.f};
        float hi[4] = {0.f, 0.f, 0.f, 0.f};
        #pragma unroll
        for (int q = 0; q < W / 4; q++) {
            const int off = (t0 + S + 4 * q + TT) & (TT - 1);
            const uint2 u = *(const uint2*)&in[off];
            const float2 f01 = __half22float2(*(const __half2*)&u.x);
            const float2 f23 = __half22float2(*(const __half2*)&u.y);
            const float elem[4] = {f01.x, f01.y, f23.x, f23.y};
            #pragma unroll
            for (int idx = 0; idx < 4; idx++) {
                const int a = S + 4 * q + idx;
                #pragma unroll
                for (int e = 0; e < 4; e++) {
                    const int diff = a - e;
                    if (diff % D == 0) {
                        const int j = 4 - diff / D;
                        if (j >= 0 && j < 8) {
                            lo[e] = fmaf(c_lo[j], elem[idx], lo[e]);
                            hi[e] = fmaf(c_hi[j], elem[idx], hi[e]);
                        }
                    }
                }
            }
        }
        store_half4(loH, t0, lo[0], lo[1], lo[2], lo[3]);
        store_half4(hiH, t0, hi[0], hi[1], hi[2], hi[3]);
    }
}

// ---------------------------------------------------------------------------
// Kernel B: per-(b,n) row — 3-level SWT, all-fp16 SMEM staging, single
// merged flush pass (both 128B-line families) with streaming stores.
// ---------------------------------------------------------------------------
__global__ __launch_bounds__(NTHREADS, 4)
void swt_patch_kernel(float* __restrict__ out)
{
    extern __shared__ __align__(16) __half smh[];

    const int b   = blockIdx.x >> 5;
    const int n   = blockIdx.x & 31;
    const int tid = threadIdx.x;

    __half* B0h = smh + OFF_B0H;   // x   -> a2
    __half* B1h = smh + OFF_B1H;   // a1  -> cA3
    __half* B2h = smh + OFF_B2H;   // cD1
    __half* B3h = smh + OFF_B3H;   // cD2
    __half* B4h = smh + OFF_B4H;   // cD3

    // Phase L: copy fp16 row into SMEM (one 16B load+store per thread).
    const __half* xin = &g_xTh[((size_t)b * NCH + n) * TT];
    {
        const int i = tid << 3;    // 8 halves per thread, 512*8 = 4096
        *(uint4*)&B0h[i] = *(const uint4*)&xin[i];
    }
    __syncthreads();

    // Phase 1 (d=1): a1 -> B1h, cD1 -> B2h
    swt_stage_h<1, -4, 12>(B0h, B1h, B2h, tid);
    __syncthreads();

    // Phase 2 (d=2): a2 -> B0h (x dead), cD2 -> B3h
    swt_stage_h<2, -8, 20>(B1h, B0h, B3h, tid);
    __syncthreads();

    // Phase 3 (d=4): cA3 -> B1h (a1 dead), cD3 -> B4h
    swt_stage_h<4, -12, 32>(B0h, B1h, B4h, tid);
    __syncthreads();

    // Phase 4: merged flush of both line families, streaming stores.
    // g -> p = g>>4, w16 = g&15, family = w16>>3, w8 = w16&7;
    // 16 consecutive lanes emit one patch's full 256B (2 lines).
    float* dstBase = out + (size_t)b * NP * 2048 + (size_t)n * 64;
    for (int g = tid; g < NP * 16; g += NTHREADS) {
        const int p      = g >> 4;
        const int w16    = g & 15;
        const int family = w16 >> 3;
        const int w8     = w16 & 7;
        const int s4     = (w8 & 3) << 2;
        const __half* src = family
            ? ((w8 < 4) ? B3h : B2h)      // ch2 = cD2, ch3 = cD1
            : ((w8 < 4) ? B1h : B4h);     // ch0 = cA3, ch1 = cD3
        const uint2 u = *(const uint2*)&src[(p << 3) + s4];
        const float2 f01 = __half22float2(*(const __half2*)&u.x);
        const float2 f23 = __half22float2(*(const __half2*)&u.y);
        __stcs((float4*)&dstBase[(size_t)p * 2048 + (w16 << 2)],
               make_float4(f01.x, f01.y, f23.x, f23.y));
    }
}

extern "C" void kernel_launch(void* const* d_in, const int* in_sizes, int n_in,
                              void* d_out, int out_size)
{
    const float* x = (const float*)d_in[0];
    float* out = (float*)d_out;
    (void)in_sizes; (void)n_in; (void)out_size;

    cudaFuncSetAttribute(swt_patch_kernel,
                         cudaFuncAttributeMaxDynamicSharedMemorySize,
                         SMEM_BYTES);

    dim3 tgrid(TT / 128, NB);
    transpose_kernel<<<tgrid, 256>>>(x);
    swt_patch_kernel<<<NB * NCH, NTHREADS, SMEM_BYTES>>>(out);
}